// round 14
// baseline (speedup 1.0000x reference)
#include <cuda_runtime.h>
#include <cuda_bf16.h>
#include <math.h>
#include <stdint.h>

// ---------------------------------------------------------------------------
// Problem dims
// ---------------------------------------------------------------------------
#define B_BATCH 16
#define T_SEQ   2048
#define D_DIM   1024
#define M_TOTAL (B_BATCH * T_SEQ)   // 32768
#define N_DIM   D_DIM
#define K_DIM   D_DIM
#define NUM_MASK 1433               // int(2048 * 0.7)

// GEMM tiling: CTA 128x256, 8 warps (2M x 4N), warp tile 64x64
#define TM 128
#define TN 256
#define TKC 64                      // 64 elements per K chunk
#define NCHUNK (K_DIM / TKC)        // 16
#define NBLK   (N_DIM / TN)         // 4
#define NTILES ((M_TOTAL / TM) * NBLK)   // 1024
#define NCTAS  148                  // persistent: one CTA per SM

// Stage (double-buffered): A_HI 16K + A_LO 16K + B_HI 32K + B_LO 32K = 96KB
#define ST_A_HI 0
#define ST_A_LO 16384
#define ST_B_HI 32768
#define ST_B_LO 65536
#define STAGE_BYTES 98304
// Single-buffered raw fp32 A tile: 128 rows x 256B = 32KB
#define SM_RAW   (2 * STAGE_BYTES)            // 196608
#define SM_PART  (SM_RAW + 32768)             // 229376 (512 floats epilogue)
#define SM_CLAIM (SM_PART + 2048)             // 231424
#define SMEM_BYTES (SM_CLAIM + 16)            // 231440 (< 232448 cap)

// ---------------------------------------------------------------------------
// Scratch (W only — X is consumed fp32 directly by the GEMM now)
// ---------------------------------------------------------------------------
__device__ __align__(16) __nv_bfloat16 g_Whi[(size_t)N_DIM * K_DIM];
__device__ __align__(16) __nv_bfloat16 g_Wlo[(size_t)N_DIM * K_DIM];
__device__ float g_scores_part[NBLK][M_TOTAL];
__device__ unsigned int g_tile_counter;

// ---------------------------------------------------------------------------
// Helpers
// ---------------------------------------------------------------------------
__device__ __forceinline__ uint32_t smem_u32(const void* p) {
    uint32_t a;
    asm("{ .reg .u64 t; cvta.to.shared.u64 t, %1; cvt.u32.u64 %0, t; }"
        : "=r"(a) : "l"(p));
    return a;
}

__device__ __forceinline__ void cp_async16(uint32_t dst, const void* src) {
    asm volatile("cp.async.cg.shared.global [%0], [%1], 16;"
                 :: "r"(dst), "l"(src) : "memory");
}
__device__ __forceinline__ void cp_commit() {
    asm volatile("cp.async.commit_group;" ::: "memory");
}

__device__ __forceinline__ void ldsm4(uint32_t* r, uint32_t addr) {
    asm volatile("ldmatrix.sync.aligned.m8n8.x4.shared.b16 {%0,%1,%2,%3}, [%4];"
                 : "=r"(r[0]), "=r"(r[1]), "=r"(r[2]), "=r"(r[3]) : "r"(addr));
}

__device__ __forceinline__ void mma16816(float* c, const uint32_t* a,
                                         uint32_t b0, uint32_t b1) {
    asm volatile("mma.sync.aligned.m16n8k16.row.col.f32.bf16.bf16.f32 "
                 "{%0,%1,%2,%3}, {%4,%5,%6,%7}, {%8,%9}, {%0,%1,%2,%3};"
                 : "+f"(c[0]), "+f"(c[1]), "+f"(c[2]), "+f"(c[3])
                 : "r"(a[0]), "r"(a[1]), "r"(a[2]), "r"(a[3]), "r"(b0), "r"(b1));
}

// Monotonic float <-> sortable-uint transform (ascending order preserved)
__device__ __forceinline__ uint32_t f2key(float f) {
    uint32_t b = __float_as_uint(f);
    return b ^ ((b & 0x80000000u) ? 0xFFFFFFFFu : 0x80000000u);
}
__device__ __forceinline__ float key2f(uint32_t k) {
    return __uint_as_float(k ^ ((k & 0x80000000u) ? 0x80000000u : 0xFFFFFFFFu));
}

// fp32 pair -> packed bf16x2 hi and lo (identical math to the old split4)
__device__ __forceinline__ void split2(float f0, float f1,
                                       uint32_t& hi, uint32_t& lo) {
    __nv_bfloat16 h0 = __float2bfloat16(f0);
    __nv_bfloat16 h1 = __float2bfloat16(f1);
    __nv_bfloat16 l0 = __float2bfloat16(f0 - __bfloat162float(h0));
    __nv_bfloat16 l1 = __float2bfloat16(f1 - __bfloat162float(h1));
    __nv_bfloat162 hv = __halves2bfloat162(h0, h1);
    __nv_bfloat162 lv = __halves2bfloat162(l0, l1);
    hi = *reinterpret_cast<uint32_t*>(&hv);
    lo = *reinterpret_cast<uint32_t*>(&lv);
}

// ---------------------------------------------------------------------------
// Kernel 0: split W fp32 -> bf16 hi/lo (4MB; ~2us). Also resets tile counter.
// ---------------------------------------------------------------------------
__global__ __launch_bounds__(256)
void split_w_kernel(const float* __restrict__ src)
{
    if (blockIdx.x == 0 && threadIdx.x == 0) g_tile_counter = 0u;

    int i = blockIdx.x * 256 + threadIdx.x;
    float4 v = ((const float4*)src)[i];
    uint32_t h0, l0, h1, l1;
    split2(v.x, v.y, h0, l0);
    split2(v.z, v.w, h1, l1);
    ((uint32_t*)g_Whi)[2 * i]     = h0;
    ((uint32_t*)g_Whi)[2 * i + 1] = h1;
    ((uint32_t*)g_Wlo)[2 * i]     = l0;
    ((uint32_t*)g_Wlo)[2 * i + 1] = l1;
}

// ---------------------------------------------------------------------------
// Kernel 1: persistent split-bf16 score GEMM with FUSED X conversion.
//   Raw fp32 A tiles stream in via cp.async (same DRAM bytes as bf16 hi+lo);
//   an in-kernel conversion phase produces the swizzled A_HI/A_LO bf16 tiles.
//   The old split_x kernel (256MB of DRAM traffic) is eliminated.
// Chunk protocol: wait cp -> barrier -> convert raw->stage s -> barrier ->
// prefetch (raw c+1 + B c+1 into s^1) -> mma stage s.
// Conversion math identical to split_x -> scores bitwise identical.
// ---------------------------------------------------------------------------
__global__ __launch_bounds__(256, 1)
void gemm_score_mma(const float* __restrict__ xg,
                    const float* __restrict__ b1, const float* __restrict__ w2)
{
    extern __shared__ char smem[];
    const uint32_t sb = smem_u32(smem);
    const int tid = threadIdx.x;
    const int wid = tid >> 5;
    const int lane = tid & 31;
    const int warp_m = wid >> 2;    // 0..1
    const int warp_n = wid & 3;     // 0..3

    int* claimp = (int*)(smem + SM_CLAIM);
    float* part = (float*)(smem + SM_PART);

#define CLAIM(dst)                                                            \
    do {                                                                      \
        if (tid == 0) *claimp = (int)atomicAdd(&g_tile_counter, 1u);          \
        __syncthreads();                                                      \
        (dst) = *claimp;                                                      \
        __syncthreads();                                                      \
    } while (0)

    int cur, nxt;
    CLAIM(cur);
    if (cur >= NTILES) return;
    CLAIM(nxt);

    int cur_m0 = (cur >> 2) * TM, cur_n0 = (cur & 3) * TN;
    int nxt_m0 = 0, nxt_n0 = 0;
    if (nxt < NTILES) { nxt_m0 = (nxt >> 2) * TM; nxt_n0 = (nxt & 3) * TN; }

    float acc[4][8][4];
#pragma unroll
    for (int a = 0; a < 4; ++a)
#pragma unroll
        for (int b = 0; b < 8; ++b)
#pragma unroll
            for (int cc = 0; cc < 4; ++cc) acc[a][b][cc] = 0.0f;

    // cp.async thread mapping
    const int urow = tid >> 3;     // B tiles: 0..31 (+32/pass)
    const int uch = tid & 7;

    // Raw A: 128 rows x 16 units(16B); thread -> rows tid>>3 (+32/pass),
    // units (tid&7)*2 + {0,1}
#define ISSUE_RAW(c, mb)                                                      \
    do {                                                                      \
        const int k0_ = (c) * TKC;                                            \
        _Pragma("unroll")                                                     \
        for (int i_ = 0; i_ < 4; ++i_) {                                      \
            const int row_ = urow + i_ * 32;                                  \
            const int u_ = uch * 2;                                           \
            const float* src_ = xg + (size_t)((mb) + row_) * K_DIM + k0_ + u_ * 4; \
            cp_async16(sb + SM_RAW + row_ * 256 + u_ * 16, src_);             \
            cp_async16(sb + SM_RAW + row_ * 256 + u_ * 16 + 16, src_ + 4);    \
        }                                                                     \
    } while (0)

#define ISSUE_B(s, c, nb)                                                     \
    do {                                                                      \
        const int k0_ = (c) * TKC;                                            \
        const uint32_t st_ = sb + (s) * STAGE_BYTES;                          \
        const __nv_bfloat16* Bh_ = g_Whi + (size_t)(nb) * K_DIM;              \
        const __nv_bfloat16* Bl_ = g_Wlo + (size_t)(nb) * K_DIM;              \
        _Pragma("unroll")                                                     \
        for (int i_ = 0; i_ < 8; ++i_) {                                      \
            const int row_ = urow + i_ * 32;                                  \
            const uint32_t sw_ = row_ * 128 + ((uch ^ (row_ & 7)) << 4);      \
            const size_t go_ = (size_t)row_ * K_DIM + k0_ + uch * 8;          \
            cp_async16(st_ + ST_B_HI + sw_, Bh_ + go_);                       \
            cp_async16(st_ + ST_B_LO + sw_, Bl_ + go_);                       \
        }                                                                     \
    } while (0)

    // Conversion mapping: thread -> row tid>>1, half tid&1 (32 floats)
    const int cr = tid >> 1;
    const int chh = tid & 1;
    const uint32_t rawbase = sb + SM_RAW + cr * 256 + chh * 128;

    // ldmatrix address components
    const int a_row = warp_m * 64 + (lane & 15);
    const int a_chsel = (lane >> 4);
    const int b_row = warp_n * 64 + ((lane >> 4) << 3) + (lane & 7);
    const int b_chsel = ((lane >> 3) & 1);

    ISSUE_RAW(0, cur_m0);
    ISSUE_B(0, 0, cur_n0);
    cp_commit();
    int s = 0;

    while (true) {
#pragma unroll 1
        for (int c = 0; c < NCHUNK; ++c) {
            asm volatile("cp.async.wait_group 0;" ::: "memory");
            __syncthreads();

            const uint32_t st = sb + s * STAGE_BYTES;

            // ---- convert raw fp32 A(c) -> bf16 hi/lo tiles in stage s ----
#pragma unroll
            for (int m = 0; m < 4; ++m) {
                float4 v0, v1;
                asm volatile("ld.shared.v4.f32 {%0,%1,%2,%3}, [%4];"
                             : "=f"(v0.x), "=f"(v0.y), "=f"(v0.z), "=f"(v0.w)
                             : "r"(rawbase + m * 32));
                asm volatile("ld.shared.v4.f32 {%0,%1,%2,%3}, [%4];"
                             : "=f"(v1.x), "=f"(v1.y), "=f"(v1.z), "=f"(v1.w)
                             : "r"(rawbase + m * 32 + 16));
                uint32_t h0, l0, h1, l1, h2, l2, h3, l3;
                split2(v0.x, v0.y, h0, l0);
                split2(v0.z, v0.w, h1, l1);
                split2(v1.x, v1.y, h2, l2);
                split2(v1.z, v1.w, h3, l3);
                const int cu = chh * 4 + m;
                const uint32_t sw = cr * 128 + ((cu ^ (cr & 7)) << 4);
                asm volatile("st.shared.v4.b32 [%0], {%1,%2,%3,%4};"
                             :: "r"(st + ST_A_HI + sw), "r"(h0), "r"(h1), "r"(h2), "r"(h3)
                             : "memory");
                asm volatile("st.shared.v4.b32 [%0], {%1,%2,%3,%4};"
                             :: "r"(st + ST_A_LO + sw), "r"(l0), "r"(l1), "r"(l2), "r"(l3)
                             : "memory");
            }
            __syncthreads();   // conversion visible; raw buffer now reusable

            if (c + 1 < NCHUNK) {
                ISSUE_RAW(c + 1, cur_m0);
                ISSUE_B(s ^ 1, c + 1, cur_n0);
                cp_commit();
            } else if (nxt < NTILES) {
                ISSUE_RAW(0, nxt_m0);
                ISSUE_B(s ^ 1, 0, nxt_n0);
                cp_commit();
            }

            // ---- MMA on stage s (term-major; order hh -> hl -> lh) ----
#pragma unroll
            for (int kk = 0; kk < 4; ++kk) {
                const int ch = kk * 2;
                uint32_t ah[4][4], bh[4][4];
#pragma unroll
                for (int mt = 0; mt < 4; ++mt) {
                    const int row = a_row + mt * 16;
                    const int cc = a_chsel + ch;
                    ldsm4(ah[mt], st + ST_A_HI + row * 128 + ((cc ^ (row & 7)) << 4));
                }
#pragma unroll
                for (int nt2 = 0; nt2 < 4; ++nt2) {
                    const int row = b_row + nt2 * 16;
                    const int cc = b_chsel + ch;
                    ldsm4(bh[nt2], st + ST_B_HI + row * 128 + ((cc ^ (row & 7)) << 4));
                }
#pragma unroll
                for (int mt = 0; mt < 4; ++mt)
#pragma unroll
                    for (int nt = 0; nt < 8; ++nt) {
                        const int nt2 = nt >> 1, hh = (nt & 1) * 2;
                        mma16816(acc[mt][nt], ah[mt], bh[nt2][hh], bh[nt2][hh + 1]);
                    }
                uint32_t bl[4][4];
#pragma unroll
                for (int nt2 = 0; nt2 < 4; ++nt2) {
                    const int row = b_row + nt2 * 16;
                    const int cc = b_chsel + ch;
                    ldsm4(bl[nt2], st + ST_B_LO + row * 128 + ((cc ^ (row & 7)) << 4));
                }
#pragma unroll
                for (int mt = 0; mt < 4; ++mt)
#pragma unroll
                    for (int nt = 0; nt < 8; ++nt) {
                        const int nt2 = nt >> 1, hh = (nt & 1) * 2;
                        mma16816(acc[mt][nt], ah[mt], bl[nt2][hh], bl[nt2][hh + 1]);
                    }
                uint32_t al[4][4];
#pragma unroll
                for (int mt = 0; mt < 4; ++mt) {
                    const int row = a_row + mt * 16;
                    const int cc = a_chsel + ch;
                    ldsm4(al[mt], st + ST_A_LO + row * 128 + ((cc ^ (row & 7)) << 4));
                }
#pragma unroll
                for (int mt = 0; mt < 4; ++mt)
#pragma unroll
                    for (int nt = 0; nt < 8; ++nt) {
                        const int nt2 = nt >> 1, hh = (nt & 1) * 2;
                        mma16816(acc[mt][nt], al[mt], bh[nt2][hh], bh[nt2][hh + 1]);
                    }
            }
            s ^= 1;
        }

        // ---------------- Epilogue for tile `cur` ----------------
        {
            const int g = lane >> 2, q = lane & 3;
            float rsum[8];
#pragma unroll
            for (int i = 0; i < 8; ++i) rsum[i] = 0.0f;
#pragma unroll
            for (int nt = 0; nt < 8; ++nt) {
                const int col0 = cur_n0 + warp_n * 64 + nt * 8 + q * 2;
                const float w0 = w2[col0],     bb0 = b1[col0];
                const float w1 = w2[col0 + 1], bb1 = b1[col0 + 1];
#pragma unroll
                for (int mt = 0; mt < 4; ++mt) {
                    rsum[mt * 2 + 0] += w0 * tanhf(acc[mt][nt][0] + bb0);
                    rsum[mt * 2 + 0] += w1 * tanhf(acc[mt][nt][1] + bb1);
                    rsum[mt * 2 + 1] += w0 * tanhf(acc[mt][nt][2] + bb0);
                    rsum[mt * 2 + 1] += w1 * tanhf(acc[mt][nt][3] + bb1);
                }
            }
#pragma unroll
            for (int i = 0; i < 8; ++i) {
                rsum[i] += __shfl_xor_sync(0xffffffffu, rsum[i], 1);
                rsum[i] += __shfl_xor_sync(0xffffffffu, rsum[i], 2);
            }
            if (q == 0) {
#pragma unroll
                for (int mt = 0; mt < 4; ++mt) {
                    part[warp_n * 128 + warp_m * 64 + mt * 16 + g]     = rsum[mt * 2 + 0];
                    part[warp_n * 128 + warp_m * 64 + mt * 16 + 8 + g] = rsum[mt * 2 + 1];
                }
            }
            __syncthreads();
            if (tid < TM) {
                const float ssum = part[tid] + part[128 + tid] +
                                   part[256 + tid] + part[384 + tid];
                g_scores_part[cur & 3][cur_m0 + tid] = ssum;
            }
        }

        if (nxt >= NTILES) break;
        cur = nxt; cur_m0 = nxt_m0; cur_n0 = nxt_n0;
        CLAIM(nxt);
        if (nxt < NTILES) { nxt_m0 = (nxt >> 2) * TM; nxt_n0 = (nxt & 3) * TN; }

#pragma unroll
        for (int a = 0; a < 4; ++a)
#pragma unroll
            for (int b = 0; b < 8; ++b)
#pragma unroll
                for (int cc = 0; cc < 4; ++cc) acc[a][b][cc] = 0.0f;
    }
}

// ---------------------------------------------------------------------------
// Kernel 2: per-batch softmax + radix-select threshold + mask -> weights
// ---------------------------------------------------------------------------
__global__ __launch_bounds__(1024)
void softmax_mask_kernel(float* __restrict__ wout)
{
    __shared__ float sv[T_SEQ];
    __shared__ unsigned int keys[T_SEQ];
    __shared__ float red[1024];
    __shared__ int hist[256];
    __shared__ int scan[256];
    __shared__ int sel_bin, sel_excl;

    const int b = blockIdx.x;
    const int tid = threadIdx.x;
    const size_t base = (size_t)b * T_SEQ;

    for (int t = tid; t < T_SEQ; t += 1024) {
        float s = 0.0f;
#pragma unroll
        for (int p = 0; p < NBLK; ++p) s += g_scores_part[p][base + t];
        sv[t] = s;
        keys[t] = f2key(s);
    }
    __syncthreads();

    unsigned int pref = 0;
    int k = NUM_MASK;
#pragma unroll
    for (int pass = 0; pass < 4; ++pass) {
        const int shift = 24 - 8 * pass;
        const unsigned int pmask = (pass == 0) ? 0u : (0xFFFFFFFFu << (shift + 8));
        if (tid < 256) hist[tid] = 0;
        __syncthreads();
        for (int t = tid; t < T_SEQ; t += 1024) {
            const unsigned int key = keys[t];
            if ((key & pmask) == pref)
                atomicAdd(&hist[(key >> shift) & 0xFF], 1);
        }
        __syncthreads();
        if (tid < 256) scan[tid] = hist[tid];
        __syncthreads();
        for (int off = 1; off < 256; off <<= 1) {
            int add = 0;
            if (tid < 256 && tid >= off) add = scan[tid - off];
            __syncthreads();
            if (tid < 256) scan[tid] += add;
            __syncthreads();
        }
        if (tid < 256) {
            const int excl = scan[tid] - hist[tid];
            if (excl <= k && k < scan[tid]) { sel_bin = tid; sel_excl = excl; }
        }
        __syncthreads();
        pref |= ((unsigned int)sel_bin) << shift;
        k -= sel_excl;
        __syncthreads();
    }
    const float thr = key2f(pref);

    float m = -INFINITY;
    for (int t = tid; t < T_SEQ; t += 1024) m = fmaxf(m, sv[t]);
    red[tid] = m;
    __syncthreads();
    for (int s = 512; s > 0; s >>= 1) {
        if (tid < s) red[tid] = fmaxf(red[tid], red[tid + s]);
        __syncthreads();
    }
    const float mx = red[0];
    __syncthreads();

    float sum = 0.0f;
    for (int t = tid; t < T_SEQ; t += 1024) sum += expf(sv[t] - mx);
    red[tid] = sum;
    __syncthreads();
    for (int s = 512; s > 0; s >>= 1) {
        if (tid < s) red[tid] += red[tid + s];
        __syncthreads();
    }
    const float inv = 1.0f / red[0];

    for (int t = tid; t < T_SEQ; t += 1024) {
        const float sc = sv[t];
        const float w = expf(sc - mx) * inv;
        wout[base + t] = (sc >= thr) ? w : 0.0f;
    }
}

// ---------------------------------------------------------------------------
// Kernel 3: masked_output = x * weights (broadcast). HBM stream.
// ---------------------------------------------------------------------------
__global__ __launch_bounds__(256)
void scale_kernel(const float* __restrict__ x,
                  const float* __restrict__ mw,
                  float* __restrict__ out)
{
    const size_t row = blockIdx.x;
    const float w = __ldg(mw + row);
    const float4* xi = (const float4*)(x + row * (size_t)D_DIM);
    float4* o = (float4*)(out + row * (size_t)D_DIM);
    const int t = threadIdx.x;
    float4 v = xi[t];
    o[t] = make_float4(v.x * w, v.y * w, v.z * w, v.w * w);
}

// ---------------------------------------------------------------------------
extern "C" void kernel_launch(void* const* d_in, const int* in_sizes, int n_in,
                              void* d_out, int out_size)
{
    const float* x  = (const float*)d_in[0];
    const float* W1 = (const float*)d_in[1];
    const float* b1 = (const float*)d_in[2];
    const float* w2 = (const float*)d_in[3];
    // b2 shifts all scores uniformly -> softmax/rank invariant; unused.
    (void)in_sizes; (void)n_in; (void)out_size;

    float* out_masked  = (float*)d_out;
    float* out_weights = out_masked + (size_t)M_TOTAL * D_DIM;

    cudaFuncSetAttribute(gemm_score_mma,
                         cudaFuncAttributeMaxDynamicSharedMemorySize, SMEM_BYTES);

    split_w_kernel<<<(N_DIM * K_DIM) / 4 / 256, 256>>>(W1);   // also resets counter

    gemm_score_mma<<<NCTAS, 256, SMEM_BYTES>>>(x, b1, w2);

    softmax_mask_kernel<<<B_BATCH, 1024>>>(out_weights);
    scale_kernel<<<M_TOTAL, 256>>>(x, out_weights, out_masked);
}

// round 15
// speedup vs baseline: 1.2148x; 1.2148x over previous
#include <cuda_runtime.h>
#include <cuda_bf16.h>
#include <math.h>
#include <stdint.h>

// ---------------------------------------------------------------------------
// Problem dims
// ---------------------------------------------------------------------------
#define B_BATCH 16
#define T_SEQ   2048
#define D_DIM   1024
#define M_TOTAL (B_BATCH * T_SEQ)   // 32768
#define N_DIM   D_DIM
#define K_DIM   D_DIM
#define NUM_MASK 1433               // int(2048 * 0.7)

// GEMM tiling: CTA 128x256, 8 warps (2M x 4N), warp tile 64x64
#define TM 128
#define TN 256
#define TKC 64                      // 64 bf16 = 128B rows
#define NCHUNK (K_DIM / TKC)        // 16
#define NBLK   (N_DIM / TN)         // 4
#define NTILES ((M_TOTAL / TM) * NBLK)   // 1024
#define NCTAS  148                  // persistent: one CTA per SM

// Stage: A 128x128B x2 (hi/lo) = 32KB, B 256x128B x2 = 64KB -> 96KB/stage
#define ST_A_HI 0
#define ST_A_LO 16384
#define ST_B_HI 32768
#define ST_B_LO 65536
#define STAGE_BYTES 98304
#define SM_PART  (2 * STAGE_BYTES)          // 512 floats epilogue scratch
#define SM_CLAIM (SM_PART + 2048)           // tile-claim broadcast slot
#define SMEM_BYTES (SM_CLAIM + 16)          // 198720

// ---------------------------------------------------------------------------
// Scratch
// ---------------------------------------------------------------------------
__device__ __align__(16) __nv_bfloat16 g_Xhi[(size_t)M_TOTAL * K_DIM];
__device__ __align__(16) __nv_bfloat16 g_Xlo[(size_t)M_TOTAL * K_DIM];
__device__ __align__(16) __nv_bfloat16 g_Whi[(size_t)N_DIM * K_DIM];
__device__ __align__(16) __nv_bfloat16 g_Wlo[(size_t)N_DIM * K_DIM];
__device__ float g_scores_part[NBLK][M_TOTAL];
__device__ unsigned int g_tile_counter;

// ---------------------------------------------------------------------------
// Helpers
// ---------------------------------------------------------------------------
__device__ __forceinline__ uint32_t smem_u32(const void* p) {
    uint32_t a;
    asm("{ .reg .u64 t; cvta.to.shared.u64 t, %1; cvt.u32.u64 %0, t; }"
        : "=r"(a) : "l"(p));
    return a;
}

__device__ __forceinline__ void cp_async16(uint32_t dst, const void* src) {
    asm volatile("cp.async.cg.shared.global [%0], [%1], 16;"
                 :: "r"(dst), "l"(src) : "memory");
}
__device__ __forceinline__ void cp_commit() {
    asm volatile("cp.async.commit_group;" ::: "memory");
}

__device__ __forceinline__ void ldsm4(uint32_t* r, uint32_t addr) {
    asm volatile("ldmatrix.sync.aligned.m8n8.x4.shared.b16 {%0,%1,%2,%3}, [%4];"
                 : "=r"(r[0]), "=r"(r[1]), "=r"(r[2]), "=r"(r[3]) : "r"(addr));
}

__device__ __forceinline__ void mma16816(float* c, const uint32_t* a,
                                         uint32_t b0, uint32_t b1) {
    asm volatile("mma.sync.aligned.m16n8k16.row.col.f32.bf16.bf16.f32 "
                 "{%0,%1,%2,%3}, {%4,%5,%6,%7}, {%8,%9}, {%0,%1,%2,%3};"
                 : "+f"(c[0]), "+f"(c[1]), "+f"(c[2]), "+f"(c[3])
                 : "r"(a[0]), "r"(a[1]), "r"(a[2]), "r"(a[3]), "r"(b0), "r"(b1));
}

// Monotonic float <-> sortable-uint transform (ascending order preserved)
__device__ __forceinline__ uint32_t f2key(float f) {
    uint32_t b = __float_as_uint(f);
    return b ^ ((b & 0x80000000u) ? 0xFFFFFFFFu : 0x80000000u);
}
__device__ __forceinline__ float key2f(uint32_t k) {
    return __uint_as_float(k ^ ((k & 0x80000000u) ? 0x80000000u : 0xFFFFFFFFu));
}

// ---------------------------------------------------------------------------
// Kernel 0: split fp32 -> bf16 hi/lo
// ---------------------------------------------------------------------------
__device__ __forceinline__ void split4(const float4 v,
                                       __nv_bfloat162* hi2, __nv_bfloat162* lo2) {
    __nv_bfloat16 h0 = __float2bfloat16(v.x);
    __nv_bfloat16 h1 = __float2bfloat16(v.y);
    __nv_bfloat16 h2 = __float2bfloat16(v.z);
    __nv_bfloat16 h3 = __float2bfloat16(v.w);
    hi2[0] = __halves2bfloat162(h0, h1);
    hi2[1] = __halves2bfloat162(h2, h3);
    lo2[0] = __halves2bfloat162(__float2bfloat16(v.x - __bfloat162float(h0)),
                                __float2bfloat16(v.y - __bfloat162float(h1)));
    lo2[1] = __halves2bfloat162(__float2bfloat16(v.z - __bfloat162float(h2)),
                                __float2bfloat16(v.w - __bfloat162float(h3)));
}

__global__ __launch_bounds__(256)
void split_x_kernel(const float* __restrict__ src)
{
    int i = blockIdx.x * 256 + threadIdx.x;
    float4 v = ((const float4*)src)[i];
    __nv_bfloat162 h[2], l[2];
    split4(v, h, l);
    ((__nv_bfloat162*)g_Xhi)[2 * i]     = h[0];
    ((__nv_bfloat162*)g_Xhi)[2 * i + 1] = h[1];
    ((__nv_bfloat162*)g_Xlo)[2 * i]     = l[0];
    ((__nv_bfloat162*)g_Xlo)[2 * i + 1] = l[1];
}

__global__ __launch_bounds__(256)
void split_w_kernel(const float* __restrict__ src)
{
    // Reset the persistent-GEMM tile counter (stream-ordered before the GEMM;
    // runs on every graph replay -> deterministic).
    if (blockIdx.x == 0 && threadIdx.x == 0) g_tile_counter = 0u;

    int i = blockIdx.x * 256 + threadIdx.x;
    float4 v = ((const float4*)src)[i];
    __nv_bfloat162 h[2], l[2];
    split4(v, h, l);
    ((__nv_bfloat162*)g_Whi)[2 * i]     = h[0];
    ((__nv_bfloat162*)g_Whi)[2 * i + 1] = h[1];
    ((__nv_bfloat162*)g_Wlo)[2 * i]     = l[0];
    ((__nv_bfloat162*)g_Wlo)[2 * i + 1] = l[1];
}

// ---------------------------------------------------------------------------
// Kernel 1: persistent split-bf16 score GEMM via mma.sync (m16n8k16).
// (identical to the 533.4us round — GEMM is at its HMMA-issue floor)
// ---------------------------------------------------------------------------
__global__ __launch_bounds__(256, 1)
void gemm_score_mma(const float* __restrict__ b1, const float* __restrict__ w2)
{
    extern __shared__ char smem[];
    const uint32_t sb = smem_u32(smem);
    const int tid = threadIdx.x;
    const int wid = tid >> 5;
    const int lane = tid & 31;
    const int warp_m = wid >> 2;    // 0..1
    const int warp_n = wid & 3;     // 0..3

    int* claimp = (int*)(smem + SM_CLAIM);
    float* part = (float*)(smem + SM_PART);

#define CLAIM(dst)                                                            \
    do {                                                                      \
        if (tid == 0) *claimp = (int)atomicAdd(&g_tile_counter, 1u);          \
        __syncthreads();                                                      \
        (dst) = *claimp;                                                      \
        __syncthreads();                                                      \
    } while (0)

    int cur, nxt;
    CLAIM(cur);
    if (cur >= NTILES) return;
    CLAIM(nxt);

    int cur_m0 = (cur >> 2) * TM, cur_n0 = (cur & 3) * TN;
    int nxt_m0 = 0, nxt_n0 = 0;
    if (nxt < NTILES) { nxt_m0 = (nxt >> 2) * TM; nxt_n0 = (nxt & 3) * TN; }

    float acc[4][8][4];
#pragma unroll
    for (int a = 0; a < 4; ++a)
#pragma unroll
        for (int b = 0; b < 8; ++b)
#pragma unroll
            for (int cc = 0; cc < 4; ++cc) acc[a][b][cc] = 0.0f;

    const int urow = tid >> 3;
    const int uch = tid & 7;

#define ISSUE_STAGE(s, c, mb, nb)                                             \
    do {                                                                      \
        const int k0_ = (c) * TKC;                                            \
        const uint32_t st_ = sb + (s) * STAGE_BYTES;                          \
        const __nv_bfloat16* Ah_ = g_Xhi + (size_t)(mb) * K_DIM;              \
        const __nv_bfloat16* Al_ = g_Xlo + (size_t)(mb) * K_DIM;              \
        const __nv_bfloat16* Bh_ = g_Whi + (size_t)(nb) * K_DIM;              \
        const __nv_bfloat16* Bl_ = g_Wlo + (size_t)(nb) * K_DIM;              \
        _Pragma("unroll")                                                     \
        for (int i_ = 0; i_ < 4; ++i_) {                                      \
            const int row_ = urow + i_ * 32;                                  \
            const uint32_t sw_ = row_ * 128 + ((uch ^ (row_ & 7)) << 4);      \
            const size_t go_ = (size_t)row_ * K_DIM + k0_ + uch * 8;          \
            cp_async16(st_ + ST_A_HI + sw_, Ah_ + go_);                       \
            cp_async16(st_ + ST_A_LO + sw_, Al_ + go_);                       \
        }                                                                     \
        _Pragma("unroll")                                                     \
        for (int i_ = 0; i_ < 8; ++i_) {                                      \
            const int row_ = urow + i_ * 32;                                  \
            const uint32_t sw_ = row_ * 128 + ((uch ^ (row_ & 7)) << 4);      \
            const size_t go_ = (size_t)row_ * K_DIM + k0_ + uch * 8;          \
            cp_async16(st_ + ST_B_HI + sw_, Bh_ + go_);                       \
            cp_async16(st_ + ST_B_LO + sw_, Bl_ + go_);                       \
        }                                                                     \
        cp_commit();                                                          \
    } while (0)

    const int a_row = warp_m * 64 + (lane & 15);
    const int a_chsel = (lane >> 4);
    const int b_row = warp_n * 64 + ((lane >> 4) << 3) + (lane & 7);
    const int b_chsel = ((lane >> 3) & 1);

    ISSUE_STAGE(0, 0, cur_m0, cur_n0);
    int s = 0;

    while (true) {
#pragma unroll 1
        for (int c = 0; c < NCHUNK; ++c) {
            asm volatile("cp.async.wait_group 0;" ::: "memory");
            __syncthreads();
            if (c + 1 < NCHUNK)        ISSUE_STAGE(s ^ 1, c + 1, cur_m0, cur_n0);
            else if (nxt < NTILES)     ISSUE_STAGE(s ^ 1, 0, nxt_m0, nxt_n0);

            const uint32_t st = sb + s * STAGE_BYTES;
#pragma unroll
            for (int kk = 0; kk < 4; ++kk) {
                const int ch = kk * 2;
                uint32_t ah[4][4], bh[4][4];
#pragma unroll
                for (int mt = 0; mt < 4; ++mt) {
                    const int row = a_row + mt * 16;
                    const int cc = a_chsel + ch;
                    ldsm4(ah[mt], st + ST_A_HI + row * 128 + ((cc ^ (row & 7)) << 4));
                }
#pragma unroll
                for (int nt2 = 0; nt2 < 4; ++nt2) {
                    const int row = b_row + nt2 * 16;
                    const int cc = b_chsel + ch;
                    ldsm4(bh[nt2], st + ST_B_HI + row * 128 + ((cc ^ (row & 7)) << 4));
                }
#pragma unroll
                for (int mt = 0; mt < 4; ++mt)
#pragma unroll
                    for (int nt = 0; nt < 8; ++nt) {
                        const int nt2 = nt >> 1, hh = (nt & 1) * 2;
                        mma16816(acc[mt][nt], ah[mt], bh[nt2][hh], bh[nt2][hh + 1]);
                    }
                uint32_t bl[4][4];
#pragma unroll
                for (int nt2 = 0; nt2 < 4; ++nt2) {
                    const int row = b_row + nt2 * 16;
                    const int cc = b_chsel + ch;
                    ldsm4(bl[nt2], st + ST_B_LO + row * 128 + ((cc ^ (row & 7)) << 4));
                }
#pragma unroll
                for (int mt = 0; mt < 4; ++mt)
#pragma unroll
                    for (int nt = 0; nt < 8; ++nt) {
                        const int nt2 = nt >> 1, hh = (nt & 1) * 2;
                        mma16816(acc[mt][nt], ah[mt], bl[nt2][hh], bl[nt2][hh + 1]);
                    }
                uint32_t al[4][4];
#pragma unroll
                for (int mt = 0; mt < 4; ++mt) {
                    const int row = a_row + mt * 16;
                    const int cc = a_chsel + ch;
                    ldsm4(al[mt], st + ST_A_LO + row * 128 + ((cc ^ (row & 7)) << 4));
                }
#pragma unroll
                for (int mt = 0; mt < 4; ++mt)
#pragma unroll
                    for (int nt = 0; nt < 8; ++nt) {
                        const int nt2 = nt >> 1, hh = (nt & 1) * 2;
                        mma16816(acc[mt][nt], al[mt], bh[nt2][hh], bh[nt2][hh + 1]);
                    }
            }
            s ^= 1;
        }

        // ---------------- Epilogue for tile `cur` ----------------
        {
            const int g = lane >> 2, q = lane & 3;
            float rsum[8];
#pragma unroll
            for (int i = 0; i < 8; ++i) rsum[i] = 0.0f;
#pragma unroll
            for (int nt = 0; nt < 8; ++nt) {
                const int col0 = cur_n0 + warp_n * 64 + nt * 8 + q * 2;
                const float w0 = w2[col0],     bb0 = b1[col0];
                const float w1 = w2[col0 + 1], bb1 = b1[col0 + 1];
#pragma unroll
                for (int mt = 0; mt < 4; ++mt) {
                    rsum[mt * 2 + 0] += w0 * tanhf(acc[mt][nt][0] + bb0);
                    rsum[mt * 2 + 0] += w1 * tanhf(acc[mt][nt][1] + bb1);
                    rsum[mt * 2 + 1] += w0 * tanhf(acc[mt][nt][2] + bb0);
                    rsum[mt * 2 + 1] += w1 * tanhf(acc[mt][nt][3] + bb1);
                }
            }
#pragma unroll
            for (int i = 0; i < 8; ++i) {
                rsum[i] += __shfl_xor_sync(0xffffffffu, rsum[i], 1);
                rsum[i] += __shfl_xor_sync(0xffffffffu, rsum[i], 2);
            }
            if (q == 0) {
#pragma unroll
                for (int mt = 0; mt < 4; ++mt) {
                    part[warp_n * 128 + warp_m * 64 + mt * 16 + g]     = rsum[mt * 2 + 0];
                    part[warp_n * 128 + warp_m * 64 + mt * 16 + 8 + g] = rsum[mt * 2 + 1];
                }
            }
            __syncthreads();
            if (tid < TM) {
                const float ssum = part[tid] + part[128 + tid] +
                                   part[256 + tid] + part[384 + tid];
                g_scores_part[cur & 3][cur_m0 + tid] = ssum;
            }
        }

        if (nxt >= NTILES) break;
        cur = nxt; cur_m0 = nxt_m0; cur_n0 = nxt_n0;
        CLAIM(nxt);
        if (nxt < NTILES) { nxt_m0 = (nxt >> 2) * TM; nxt_n0 = (nxt & 3) * TN; }

#pragma unroll
        for (int a = 0; a < 4; ++a)
#pragma unroll
            for (int b = 0; b < 8; ++b)
#pragma unroll
                for (int cc = 0; cc < 4; ++cc) acc[a][b][cc] = 0.0f;
    }
}

// ---------------------------------------------------------------------------
// Kernel 2: per-batch softmax + radix-select threshold + mask -> weights.
// Radix-select scan now uses warp-shfl (3 syncs/pass instead of ~16).
// Selection is exact -> threshold identical to the sort-based version.
// ---------------------------------------------------------------------------
__global__ __launch_bounds__(1024)
void softmax_mask_kernel(float* __restrict__ wout)
{
    __shared__ float sv[T_SEQ];
    __shared__ unsigned int keys[T_SEQ];
    __shared__ float red[1024];
    __shared__ int hist[256];
    __shared__ int wsum[8];
    __shared__ int sel_bin, sel_excl;

    const int b = blockIdx.x;
    const int tid = threadIdx.x;
    const size_t base = (size_t)b * T_SEQ;

    for (int t = tid; t < T_SEQ; t += 1024) {
        float s = 0.0f;
#pragma unroll
        for (int p = 0; p < NBLK; ++p) s += g_scores_part[p][base + t];
        sv[t] = s;
        keys[t] = f2key(s);
    }
    __syncthreads();

    unsigned int pref = 0;
    int k = NUM_MASK;
#pragma unroll
    for (int pass = 0; pass < 4; ++pass) {
        const int shift = 24 - 8 * pass;
        const unsigned int pmask = (pass == 0) ? 0u : (0xFFFFFFFFu << (shift + 8));
        if (tid < 256) hist[tid] = 0;
        __syncthreads();
        for (int t = tid; t < T_SEQ; t += 1024) {
            const unsigned int key = keys[t];
            if ((key & pmask) == pref)
                atomicAdd(&hist[(key >> shift) & 0xFF], 1);
        }
        __syncthreads();
        int incl = 0, hv = 0;
        if (tid < 256) {
            const int l = tid & 31;
            hv = hist[tid];
            incl = hv;
#pragma unroll
            for (int off = 1; off < 32; off <<= 1) {
                int n = __shfl_up_sync(0xffffffffu, incl, off);
                if (l >= off) incl += n;
            }
            if (l == 31) wsum[tid >> 5] = incl;
        }
        __syncthreads();
        if (tid < 256) {
            const int w = tid >> 5;
            int add = 0;
#pragma unroll
            for (int j = 0; j < 7; ++j)
                if (j < w) add += wsum[j];
            incl += add;
            const int excl = incl - hv;
            if (excl <= k && k < incl) { sel_bin = tid; sel_excl = excl; }
        }
        __syncthreads();
        pref |= ((unsigned int)sel_bin) << shift;
        k -= sel_excl;
        __syncthreads();
    }
    const float thr = key2f(pref);   // smallest KEPT score (exact rank select)

    float m = -INFINITY;
    for (int t = tid; t < T_SEQ; t += 1024) m = fmaxf(m, sv[t]);
    red[tid] = m;
    __syncthreads();
    for (int s = 512; s > 0; s >>= 1) {
        if (tid < s) red[tid] = fmaxf(red[tid], red[tid + s]);
        __syncthreads();
    }
    const float mx = red[0];
    __syncthreads();

    float sum = 0.0f;
    for (int t = tid; t < T_SEQ; t += 1024) sum += expf(sv[t] - mx);
    red[tid] = sum;
    __syncthreads();
    for (int s = 512; s > 0; s >>= 1) {
        if (tid < s) red[tid] += red[tid + s];
        __syncthreads();
    }
    const float inv = 1.0f / red[0];

    for (int t = tid; t < T_SEQ; t += 1024) {
        const float sc = sv[t];
        const float w = expf(sc - mx) * inv;
        wout[base + t] = (sc >= thr) ? w : 0.0f;
    }
}

// ---------------------------------------------------------------------------
// Kernel 3: masked_output = x * weights. 8 rows per block, 8 independent
// float4 loads in flight per thread (MLP), streaming stores.
// ---------------------------------------------------------------------------
__global__ __launch_bounds__(256)
void scale_kernel(const float* __restrict__ x,
                  const float* __restrict__ mw,
                  float* __restrict__ out)
{
    const size_t row0 = (size_t)blockIdx.x * 8;
    const int t = threadIdx.x;
    const float4* xi = (const float4*)(x + row0 * D_DIM);
    float4* o = (float4*)(out + row0 * D_DIM);

    float4 v[8];
    float w[8];
#pragma unroll
    for (int r = 0; r < 8; ++r) {
        v[r] = __ldg(xi + (size_t)r * 256 + t);
        w[r] = __ldg(mw + row0 + r);
    }
#pragma unroll
    for (int r = 0; r < 8; ++r) {
        float4 ov = make_float4(v[r].x * w[r], v[r].y * w[r],
                                v[r].z * w[r], v[r].w * w[r]);
        __stcs(o + (size_t)r * 256 + t, ov);
    }
}

// ---------------------------------------------------------------------------
extern "C" void kernel_launch(void* const* d_in, const int* in_sizes, int n_in,
                              void* d_out, int out_size)
{
    const float* x  = (const float*)d_in[0];
    const float* W1 = (const float*)d_in[1];
    const float* b1 = (const float*)d_in[2];
    const float* w2 = (const float*)d_in[3];
    // b2 shifts all scores uniformly -> softmax/rank invariant; unused.
    (void)in_sizes; (void)n_in; (void)out_size;

    float* out_masked  = (float*)d_out;
    float* out_weights = out_masked + (size_t)M_TOTAL * D_DIM;

    cudaFuncSetAttribute(gemm_score_mma,
                         cudaFuncAttributeMaxDynamicSharedMemorySize, SMEM_BYTES);

    split_x_kernel<<<(M_TOTAL * K_DIM) / 4 / 256, 256>>>(x);
    split_w_kernel<<<(N_DIM * K_DIM) / 4 / 256, 256>>>(W1);   // also resets counter

    gemm_score_mma<<<NCTAS, 256, SMEM_BYTES>>>(b1, w2);

    softmax_mask_kernel<<<B_BATCH, 1024>>>(out_weights);
    scale_kernel<<<M_TOTAL / 8, 256>>>(x, out_weights, out_masked);
}

// round 16
// speedup vs baseline: 1.2399x; 1.0207x over previous
#include <cuda_runtime.h>
#include <cuda_bf16.h>
#include <math.h>
#include <stdint.h>

// ---------------------------------------------------------------------------
// Problem dims
// ---------------------------------------------------------------------------
#define B_BATCH 16
#define T_SEQ   2048
#define D_DIM   1024
#define M_TOTAL (B_BATCH * T_SEQ)   // 32768
#define N_DIM   D_DIM
#define K_DIM   D_DIM
#define NUM_MASK 1433               // int(2048 * 0.7)

// GEMM tiling: CTA 128x256, 8 warps (2M x 4N), warp tile 64x64
#define TM 128
#define TN 256
#define TKC 64                      // 64 bf16 = 128B rows
#define NCHUNK (K_DIM / TKC)        // 16
#define NBLK   (N_DIM / TN)         // 4
#define NTILES ((M_TOTAL / TM) * NBLK)   // 1024
#define NCTAS  148                  // persistent: one CTA per SM

// Stage: A 128x128B x2 (hi/lo) = 32KB, B 256x128B x2 = 64KB -> 96KB/stage
#define ST_A_HI 0
#define ST_A_LO 16384
#define ST_B_HI 32768
#define ST_B_LO 65536
#define STAGE_BYTES 98304
#define SM_PART  (2 * STAGE_BYTES)          // 512 floats epilogue scratch
#define SM_CLAIM (SM_PART + 2048)           // tile-claim broadcast slot
#define SMEM_BYTES (SM_CLAIM + 16)          // 198720

// ---------------------------------------------------------------------------
// Scratch
// ---------------------------------------------------------------------------
__device__ __align__(16) __nv_bfloat16 g_Xhi[(size_t)M_TOTAL * K_DIM];
__device__ __align__(16) __nv_bfloat16 g_Xlo[(size_t)M_TOTAL * K_DIM];
__device__ __align__(16) __nv_bfloat16 g_Whi[(size_t)N_DIM * K_DIM];
__device__ __align__(16) __nv_bfloat16 g_Wlo[(size_t)N_DIM * K_DIM];
__device__ float g_scores_part[NBLK][M_TOTAL];
__device__ unsigned int g_tile_counter;

// ---------------------------------------------------------------------------
// Helpers
// ---------------------------------------------------------------------------
__device__ __forceinline__ uint32_t smem_u32(const void* p) {
    uint32_t a;
    asm("{ .reg .u64 t; cvta.to.shared.u64 t, %1; cvt.u32.u64 %0, t; }"
        : "=r"(a) : "l"(p));
    return a;
}

__device__ __forceinline__ void cp_async16(uint32_t dst, const void* src) {
    asm volatile("cp.async.cg.shared.global [%0], [%1], 16;"
                 :: "r"(dst), "l"(src) : "memory");
}
__device__ __forceinline__ void cp_commit() {
    asm volatile("cp.async.commit_group;" ::: "memory");
}

__device__ __forceinline__ void ldsm4(uint32_t* r, uint32_t addr) {
    asm volatile("ldmatrix.sync.aligned.m8n8.x4.shared.b16 {%0,%1,%2,%3}, [%4];"
                 : "=r"(r[0]), "=r"(r[1]), "=r"(r[2]), "=r"(r[3]) : "r"(addr));
}

__device__ __forceinline__ void mma16816(float* c, const uint32_t* a,
                                         uint32_t b0, uint32_t b1) {
    asm volatile("mma.sync.aligned.m16n8k16.row.col.f32.bf16.bf16.f32 "
                 "{%0,%1,%2,%3}, {%4,%5,%6,%7}, {%8,%9}, {%0,%1,%2,%3};"
                 : "+f"(c[0]), "+f"(c[1]), "+f"(c[2]), "+f"(c[3])
                 : "r"(a[0]), "r"(a[1]), "r"(a[2]), "r"(a[3]), "r"(b0), "r"(b1));
}

// Monotonic float <-> sortable-uint transform (ascending order preserved)
__device__ __forceinline__ uint32_t f2key(float f) {
    uint32_t b = __float_as_uint(f);
    return b ^ ((b & 0x80000000u) ? 0xFFFFFFFFu : 0x80000000u);
}
__device__ __forceinline__ float key2f(uint32_t k) {
    return __uint_as_float(k ^ ((k & 0x80000000u) ? 0x80000000u : 0xFFFFFFFFu));
}

// ---------------------------------------------------------------------------
// Kernel 0: split fp32 -> bf16 hi/lo
// ---------------------------------------------------------------------------
__device__ __forceinline__ void split4(const float4 v,
                                       __nv_bfloat162* hi2, __nv_bfloat162* lo2) {
    __nv_bfloat16 h0 = __float2bfloat16(v.x);
    __nv_bfloat16 h1 = __float2bfloat16(v.y);
    __nv_bfloat16 h2 = __float2bfloat16(v.z);
    __nv_bfloat16 h3 = __float2bfloat16(v.w);
    hi2[0] = __halves2bfloat162(h0, h1);
    hi2[1] = __halves2bfloat162(h2, h3);
    lo2[0] = __halves2bfloat162(__float2bfloat16(v.x - __bfloat162float(h0)),
                                __float2bfloat16(v.y - __bfloat162float(h1)));
    lo2[1] = __halves2bfloat162(__float2bfloat16(v.z - __bfloat162float(h2)),
                                __float2bfloat16(v.w - __bfloat162float(h3)));
}

__global__ __launch_bounds__(256)
void split_x_kernel(const float* __restrict__ src)
{
    int i = blockIdx.x * 256 + threadIdx.x;
    float4 v = ((const float4*)src)[i];
    __nv_bfloat162 h[2], l[2];
    split4(v, h, l);
    ((__nv_bfloat162*)g_Xhi)[2 * i]     = h[0];
    ((__nv_bfloat162*)g_Xhi)[2 * i + 1] = h[1];
    ((__nv_bfloat162*)g_Xlo)[2 * i]     = l[0];
    ((__nv_bfloat162*)g_Xlo)[2 * i + 1] = l[1];
}

__global__ __launch_bounds__(256)
void split_w_kernel(const float* __restrict__ src)
{
    // Reset the persistent-GEMM tile counter (stream-ordered before the GEMM;
    // runs on every graph replay -> deterministic).
    if (blockIdx.x == 0 && threadIdx.x == 0) g_tile_counter = 0u;

    int i = blockIdx.x * 256 + threadIdx.x;
    float4 v = ((const float4*)src)[i];
    __nv_bfloat162 h[2], l[2];
    split4(v, h, l);
    ((__nv_bfloat162*)g_Whi)[2 * i]     = h[0];
    ((__nv_bfloat162*)g_Whi)[2 * i + 1] = h[1];
    ((__nv_bfloat162*)g_Wlo)[2 * i]     = l[0];
    ((__nv_bfloat162*)g_Wlo)[2 * i + 1] = l[1];
}

// ---------------------------------------------------------------------------
// Kernel 1: persistent split-bf16 score GEMM via mma.sync (m16n8k16).
// (identical to the 531.0us round — GEMM is at its HMMA-issue floor)
// ---------------------------------------------------------------------------
__global__ __launch_bounds__(256, 1)
void gemm_score_mma(const float* __restrict__ b1, const float* __restrict__ w2)
{
    extern __shared__ char smem[];
    const uint32_t sb = smem_u32(smem);
    const int tid = threadIdx.x;
    const int wid = tid >> 5;
    const int lane = tid & 31;
    const int warp_m = wid >> 2;    // 0..1
    const int warp_n = wid & 3;     // 0..3

    int* claimp = (int*)(smem + SM_CLAIM);
    float* part = (float*)(smem + SM_PART);

#define CLAIM(dst)                                                            \
    do {                                                                      \
        if (tid == 0) *claimp = (int)atomicAdd(&g_tile_counter, 1u);          \
        __syncthreads();                                                      \
        (dst) = *claimp;                                                      \
        __syncthreads();                                                      \
    } while (0)

    int cur, nxt;
    CLAIM(cur);
    if (cur >= NTILES) return;
    CLAIM(nxt);

    int cur_m0 = (cur >> 2) * TM, cur_n0 = (cur & 3) * TN;
    int nxt_m0 = 0, nxt_n0 = 0;
    if (nxt < NTILES) { nxt_m0 = (nxt >> 2) * TM; nxt_n0 = (nxt & 3) * TN; }

    float acc[4][8][4];
#pragma unroll
    for (int a = 0; a < 4; ++a)
#pragma unroll
        for (int b = 0; b < 8; ++b)
#pragma unroll
            for (int cc = 0; cc < 4; ++cc) acc[a][b][cc] = 0.0f;

    const int urow = tid >> 3;
    const int uch = tid & 7;

#define ISSUE_STAGE(s, c, mb, nb)                                             \
    do {                                                                      \
        const int k0_ = (c) * TKC;                                            \
        const uint32_t st_ = sb + (s) * STAGE_BYTES;                          \
        const __nv_bfloat16* Ah_ = g_Xhi + (size_t)(mb) * K_DIM;              \
        const __nv_bfloat16* Al_ = g_Xlo + (size_t)(mb) * K_DIM;              \
        const __nv_bfloat16* Bh_ = g_Whi + (size_t)(nb) * K_DIM;              \
        const __nv_bfloat16* Bl_ = g_Wlo + (size_t)(nb) * K_DIM;              \
        _Pragma("unroll")                                                     \
        for (int i_ = 0; i_ < 4; ++i_) {                                      \
            const int row_ = urow + i_ * 32;                                  \
            const uint32_t sw_ = row_ * 128 + ((uch ^ (row_ & 7)) << 4);      \
            const size_t go_ = (size_t)row_ * K_DIM + k0_ + uch * 8;          \
            cp_async16(st_ + ST_A_HI + sw_, Ah_ + go_);                       \
            cp_async16(st_ + ST_A_LO + sw_, Al_ + go_);                       \
        }                                                                     \
        _Pragma("unroll")                                                     \
        for (int i_ = 0; i_ < 8; ++i_) {                                      \
            const int row_ = urow + i_ * 32;                                  \
            const uint32_t sw_ = row_ * 128 + ((uch ^ (row_ & 7)) << 4);      \
            const size_t go_ = (size_t)row_ * K_DIM + k0_ + uch * 8;          \
            cp_async16(st_ + ST_B_HI + sw_, Bh_ + go_);                       \
            cp_async16(st_ + ST_B_LO + sw_, Bl_ + go_);                       \
        }                                                                     \
        cp_commit();                                                          \
    } while (0)

    const int a_row = warp_m * 64 + (lane & 15);
    const int a_chsel = (lane >> 4);
    const int b_row = warp_n * 64 + ((lane >> 4) << 3) + (lane & 7);
    const int b_chsel = ((lane >> 3) & 1);

    ISSUE_STAGE(0, 0, cur_m0, cur_n0);
    int s = 0;

    while (true) {
#pragma unroll 1
        for (int c = 0; c < NCHUNK; ++c) {
            asm volatile("cp.async.wait_group 0;" ::: "memory");
            __syncthreads();
            if (c + 1 < NCHUNK)        ISSUE_STAGE(s ^ 1, c + 1, cur_m0, cur_n0);
            else if (nxt < NTILES)     ISSUE_STAGE(s ^ 1, 0, nxt_m0, nxt_n0);

            const uint32_t st = sb + s * STAGE_BYTES;
#pragma unroll
            for (int kk = 0; kk < 4; ++kk) {
                const int ch = kk * 2;
                uint32_t ah[4][4], bh[4][4];
#pragma unroll
                for (int mt = 0; mt < 4; ++mt) {
                    const int row = a_row + mt * 16;
                    const int cc = a_chsel + ch;
                    ldsm4(ah[mt], st + ST_A_HI + row * 128 + ((cc ^ (row & 7)) << 4));
                }
#pragma unroll
                for (int nt2 = 0; nt2 < 4; ++nt2) {
                    const int row = b_row + nt2 * 16;
                    const int cc = b_chsel + ch;
                    ldsm4(bh[nt2], st + ST_B_HI + row * 128 + ((cc ^ (row & 7)) << 4));
                }
#pragma unroll
                for (int mt = 0; mt < 4; ++mt)
#pragma unroll
                    for (int nt = 0; nt < 8; ++nt) {
                        const int nt2 = nt >> 1, hh = (nt & 1) * 2;
                        mma16816(acc[mt][nt], ah[mt], bh[nt2][hh], bh[nt2][hh + 1]);
                    }
                uint32_t bl[4][4];
#pragma unroll
                for (int nt2 = 0; nt2 < 4; ++nt2) {
                    const int row = b_row + nt2 * 16;
                    const int cc = b_chsel + ch;
                    ldsm4(bl[nt2], st + ST_B_LO + row * 128 + ((cc ^ (row & 7)) << 4));
                }
#pragma unroll
                for (int mt = 0; mt < 4; ++mt)
#pragma unroll
                    for (int nt = 0; nt < 8; ++nt) {
                        const int nt2 = nt >> 1, hh = (nt & 1) * 2;
                        mma16816(acc[mt][nt], ah[mt], bl[nt2][hh], bl[nt2][hh + 1]);
                    }
                uint32_t al[4][4];
#pragma unroll
                for (int mt = 0; mt < 4; ++mt) {
                    const int row = a_row + mt * 16;
                    const int cc = a_chsel + ch;
                    ldsm4(al[mt], st + ST_A_LO + row * 128 + ((cc ^ (row & 7)) << 4));
                }
#pragma unroll
                for (int mt = 0; mt < 4; ++mt)
#pragma unroll
                    for (int nt = 0; nt < 8; ++nt) {
                        const int nt2 = nt >> 1, hh = (nt & 1) * 2;
                        mma16816(acc[mt][nt], al[mt], bh[nt2][hh], bh[nt2][hh + 1]);
                    }
            }
            s ^= 1;
        }

        // ---------------- Epilogue for tile `cur` ----------------
        {
            const int g = lane >> 2, q = lane & 3;
            float rsum[8];
#pragma unroll
            for (int i = 0; i < 8; ++i) rsum[i] = 0.0f;
#pragma unroll
            for (int nt = 0; nt < 8; ++nt) {
                const int col0 = cur_n0 + warp_n * 64 + nt * 8 + q * 2;
                const float w0 = w2[col0],     bb0 = b1[col0];
                const float w1 = w2[col0 + 1], bb1 = b1[col0 + 1];
#pragma unroll
                for (int mt = 0; mt < 4; ++mt) {
                    rsum[mt * 2 + 0] += w0 * tanhf(acc[mt][nt][0] + bb0);
                    rsum[mt * 2 + 0] += w1 * tanhf(acc[mt][nt][1] + bb1);
                    rsum[mt * 2 + 1] += w0 * tanhf(acc[mt][nt][2] + bb0);
                    rsum[mt * 2 + 1] += w1 * tanhf(acc[mt][nt][3] + bb1);
                }
            }
#pragma unroll
            for (int i = 0; i < 8; ++i) {
                rsum[i] += __shfl_xor_sync(0xffffffffu, rsum[i], 1);
                rsum[i] += __shfl_xor_sync(0xffffffffu, rsum[i], 2);
            }
            if (q == 0) {
#pragma unroll
                for (int mt = 0; mt < 4; ++mt) {
                    part[warp_n * 128 + warp_m * 64 + mt * 16 + g]     = rsum[mt * 2 + 0];
                    part[warp_n * 128 + warp_m * 64 + mt * 16 + 8 + g] = rsum[mt * 2 + 1];
                }
            }
            __syncthreads();
            if (tid < TM) {
                const float ssum = part[tid] + part[128 + tid] +
                                   part[256 + tid] + part[384 + tid];
                g_scores_part[cur & 3][cur_m0 + tid] = ssum;
            }
        }

        if (nxt >= NTILES) break;
        cur = nxt; cur_m0 = nxt_m0; cur_n0 = nxt_n0;
        CLAIM(nxt);
        if (nxt < NTILES) { nxt_m0 = (nxt >> 2) * TM; nxt_n0 = (nxt & 3) * TN; }

#pragma unroll
        for (int a = 0; a < 4; ++a)
#pragma unroll
            for (int b = 0; b < 8; ++b)
#pragma unroll
                for (int cc = 0; cc < 4; ++cc) acc[a][b][cc] = 0.0f;
    }
}

// ---------------------------------------------------------------------------
// Kernel 2: per-batch softmax + radix-select threshold + mask -> weights.
// (identical to the 531.0us round)
// ---------------------------------------------------------------------------
__global__ __launch_bounds__(1024)
void softmax_mask_kernel(float* __restrict__ wout)
{
    __shared__ float sv[T_SEQ];
    __shared__ unsigned int keys[T_SEQ];
    __shared__ float red[1024];
    __shared__ int hist[256];
    __shared__ int wsum[8];
    __shared__ int sel_bin, sel_excl;

    const int b = blockIdx.x;
    const int tid = threadIdx.x;
    const size_t base = (size_t)b * T_SEQ;

    for (int t = tid; t < T_SEQ; t += 1024) {
        float s = 0.0f;
#pragma unroll
        for (int p = 0; p < NBLK; ++p) s += g_scores_part[p][base + t];
        sv[t] = s;
        keys[t] = f2key(s);
    }
    __syncthreads();

    unsigned int pref = 0;
    int k = NUM_MASK;
#pragma unroll
    for (int pass = 0; pass < 4; ++pass) {
        const int shift = 24 - 8 * pass;
        const unsigned int pmask = (pass == 0) ? 0u : (0xFFFFFFFFu << (shift + 8));
        if (tid < 256) hist[tid] = 0;
        __syncthreads();
        for (int t = tid; t < T_SEQ; t += 1024) {
            const unsigned int key = keys[t];
            if ((key & pmask) == pref)
                atomicAdd(&hist[(key >> shift) & 0xFF], 1);
        }
        __syncthreads();
        int incl = 0, hv = 0;
        if (tid < 256) {
            const int l = tid & 31;
            hv = hist[tid];
            incl = hv;
#pragma unroll
            for (int off = 1; off < 32; off <<= 1) {
                int n = __shfl_up_sync(0xffffffffu, incl, off);
                if (l >= off) incl += n;
            }
            if (l == 31) wsum[tid >> 5] = incl;
        }
        __syncthreads();
        if (tid < 256) {
            const int w = tid >> 5;
            int add = 0;
#pragma unroll
            for (int j = 0; j < 7; ++j)
                if (j < w) add += wsum[j];
            incl += add;
            const int excl = incl - hv;
            if (excl <= k && k < incl) { sel_bin = tid; sel_excl = excl; }
        }
        __syncthreads();
        pref |= ((unsigned int)sel_bin) << shift;
        k -= sel_excl;
        __syncthreads();
    }
    const float thr = key2f(pref);   // smallest KEPT score (exact rank select)

    float m = -INFINITY;
    for (int t = tid; t < T_SEQ; t += 1024) m = fmaxf(m, sv[t]);
    red[tid] = m;
    __syncthreads();
    for (int s = 512; s > 0; s >>= 1) {
        if (tid < s) red[tid] = fmaxf(red[tid], red[tid + s]);
        __syncthreads();
    }
    const float mx = red[0];
    __syncthreads();

    float sum = 0.0f;
    for (int t = tid; t < T_SEQ; t += 1024) sum += expf(sv[t] - mx);
    red[tid] = sum;
    __syncthreads();
    for (int s = 512; s > 0; s >>= 1) {
        if (tid < s) red[tid] += red[tid + s];
        __syncthreads();
    }
    const float inv = 1.0f / red[0];

    for (int t = tid; t < T_SEQ; t += 1024) {
        const float sc = sv[t];
        const float w = expf(sc - mx) * inv;
        wout[base + t] = (sc >= thr) ? w : 0.0f;
    }
}

// ---------------------------------------------------------------------------
// Kernel 3: masked_output = x * weights. 8 rows per block.
// MASK-AWARE: 70% of rows have weight == exactly 0.0f (written by the mask);
// for those, skip the x read entirely and store zeros (x*0 differs only in
// zero-sign, invisible to relative error). Cuts read traffic 128MB -> ~38MB.
// Branch is uniform across the block (all threads handle the same rows).
// ---------------------------------------------------------------------------
__global__ __launch_bounds__(256)
void scale_kernel(const float* __restrict__ x,
                  const float* __restrict__ mw,
                  float* __restrict__ out)
{
    const size_t row0 = (size_t)blockIdx.x * 8;
    const int t = threadIdx.x;
    const float4* xi = (const float4*)(x + row0 * D_DIM);
    float4* o = (float4*)(out + row0 * D_DIM);

    float w[8];
#pragma unroll
    for (int r = 0; r < 8; ++r) w[r] = __ldg(mw + row0 + r);

    float4 v[8];
#pragma unroll
    for (int r = 0; r < 8; ++r) {
        if (w[r] != 0.0f) v[r] = __ldg(xi + (size_t)r * 256 + t);
        else              v[r] = make_float4(0.0f, 0.0f, 0.0f, 0.0f);
    }
#pragma unroll
    for (int r = 0; r < 8; ++r) {
        float4 ov = make_float4(v[r].x * w[r], v[r].y * w[r],
                                v[r].z * w[r], v[r].w * w[r]);
        __stcs(o + (size_t)r * 256 + t, ov);
    }
}

// ---------------------------------------------------------------------------
extern "C" void kernel_launch(void* const* d_in, const int* in_sizes, int n_in,
                              void* d_out, int out_size)
{
    const float* x  = (const float*)d_in[0];
    const float* W1 = (const float*)d_in[1];
    const float* b1 = (const float*)d_in[2];
    const float* w2 = (const float*)d_in[3];
    // b2 shifts all scores uniformly -> softmax/rank invariant; unused.
    (void)in_sizes; (void)n_in; (void)out_size;

    float* out_masked  = (float*)d_out;
    float* out_weights = out_masked + (size_t)M_TOTAL * D_DIM;

    cudaFuncSetAttribute(gemm_score_mma,
                         cudaFuncAttributeMaxDynamicSharedMemorySize, SMEM_BYTES);

    split_x_kernel<<<(M_TOTAL * K_DIM) / 4 / 256, 256>>>(x);
    split_w_kernel<<<(N_DIM * K_DIM) / 4 / 256, 256>>>(W1);   // also resets counter

    gemm_score_mma<<<NCTAS, 256, SMEM_BYTES>>>(b1, w2);

    softmax_mask_kernel<<<B_BATCH, 1024>>>(out_weights);
    scale_kernel<<<M_TOTAL / 8, 256>>>(x, out_weights, out_masked);
}